// round 7
// baseline (speedup 1.0000x reference)
#include <cuda_runtime.h>

#define Bn 8
#define Tn 100
#define BT 800
#define Nn 100000
#define NBLK 592
#define PER 169                 // ceil(Nn / NBLK); 592*169 = 100048
#define MARGINF 0.1f
#define THRESHF 0.5f

// Zero-initialized device state. Invariant: every launch begins AND ends with
// g_key[]==0, g_done==0 (last block resets). cmax >= 0 always, so raw float
// bits are unsigned-monotone; bits(0.0f)==0 matches the zero init.
__device__ unsigned int g_key[BT];
__device__ unsigned int g_done;

__global__ void __launch_bounds__(BT, 2) kMain(
    const float* __restrict__ outputs,      // (8,100,3)
    const float* __restrict__ c2ws,         // (8,4,4)
    const float* __restrict__ sscales,      // (8,)
    const float* __restrict__ means,        // (100000,3)
    const float* __restrict__ scales,       // (100000,3)
    float* __restrict__ out)
{
    extern __shared__ char sdyn[];
    float4* s_l4 = (float4*)sdyn;                                   // [Bn][PER] {x,y,z,m2}
    float*  s_lr = (float*)(sdyn + (size_t)Bn * PER * sizeof(float4)); // [Bn][PER] radM

    __shared__ float s_r[BT * 3];
    __shared__ float s_lo[Bn * 3], s_hi[Bn * 3];
    __shared__ int   s_cnt[Bn];
    __shared__ float s_part[32];
    __shared__ int   s_last;

    const int tid = threadIdx.x;
    const int b   = tid / Tn;

    // ---- prologue: retrajs (each thread its own bt, kept in regs) ------
    float rx, ry, rz;
    {
        float ssb = sscales[b];
        float o0 = outputs[tid * 3 + 0];
        float o1 = outputs[tid * 3 + 1];
        float o2 = outputs[tid * 3 + 2];
        const float* c = c2ws + b * 16;
        rx = fmaf(ssb, o0 * c[0]  + o1 * c[1]  + o2 * c[2],  c[3]);
        ry = fmaf(ssb, o0 * c[4]  + o1 * c[5]  + o2 * c[6],  c[7]);
        rz = fmaf(ssb, o0 * c[8]  + o1 * c[9]  + o2 * c[10], c[11]);
        s_r[tid * 3 + 0] = rx;
        s_r[tid * 3 + 1] = ry;
        s_r[tid * 3 + 2] = rz;
    }
    if (tid < Bn) s_cnt[tid] = 0;
    __syncthreads();

    // ---- per-b boxes: one warp per (b,e), lane-strided + shfl reduce ---
    {
        int w = tid >> 5, l = tid & 31;
        if (w < Bn * 3) {
            int bb = w / 3, e = w % 3;
            float lo = 3.4e38f, hi = -3.4e38f;
            for (int t = l; t < Tn; t += 32) {
                float v = s_r[(bb * Tn + t) * 3 + e];
                lo = fminf(lo, v); hi = fmaxf(hi, v);
            }
#pragma unroll
            for (int o = 16; o > 0; o >>= 1) {
                lo = fminf(lo, __shfl_xor_sync(0xffffffffu, lo, o));
                hi = fmaxf(hi, __shfl_xor_sync(0xffffffffu, hi, o));
            }
            if (l == 0) {
                float thres = THRESHF * sscales[0];
                s_lo[w] = lo - thres;
                s_hi[w] = hi + thres;
            }
        }
    }
    __syncthreads();

    // ---- stage block's slice, compacted per-b (warp-aggregated) --------
    {
        int n0 = blockIdx.x * PER;
        int cnt_here = min(Nn - n0, PER);          // <= 169 < BT: single pass
        bool act = tid < cnt_here;
        float mx = 0.f, my = 0.f, mz = 0.f, m2 = 0.f, radM = 0.f;
        if (act) {
            int n = n0 + tid;
            mx = means[n * 3 + 0]; my = means[n * 3 + 1]; mz = means[n * 3 + 2];
            float a0 = scales[n * 3 + 0], a1 = scales[n * 3 + 1], a2 = scales[n * 3 + 2];
            radM = fmaxf(a0, fmaxf(a1, a2)) + MARGINF;
            m2 = fmaf(mx, mx, fmaf(my, my, mz * mz));
        }
        unsigned lmask = (1u << (tid & 31)) - 1u;
#pragma unroll
        for (int bb = 0; bb < Bn; bb++) {
            bool in = act &&
                mx >= s_lo[bb * 3 + 0] && mx <= s_hi[bb * 3 + 0] &&
                my >= s_lo[bb * 3 + 1] && my <= s_hi[bb * 3 + 1] &&
                mz >= s_lo[bb * 3 + 2] && mz <= s_hi[bb * 3 + 2];
            unsigned bal = __ballot_sync(0xffffffffu, in);
            if (bal) {
                int leader = __ffs(bal) - 1;
                int base = 0;
                if ((tid & 31) == leader) base = atomicAdd(&s_cnt[bb], __popc(bal));
                base = __shfl_sync(0xffffffffu, base, leader);
                if (in) {
                    int idx = bb * PER + base + __popc(bal & lmask);
                    s_l4[idx] = make_float4(mx, my, mz, m2);
                    s_lr[idx] = radM;
                }
            }
        }
    }
    __syncthreads();

    // ---- main loop: 5 fma-class ops per pair ---------------------------
    float cmax = 0.0f;
    {
        float n2x = -2.0f * rx, n2y = -2.0f * ry, n2z = -2.0f * rz;
        float r2 = fmaf(rx, rx, fmaf(ry, ry, rz * rz));
        const float4* l4 = s_l4 + b * PER;
        const float*  lr = s_lr + b * PER;
        int n = s_cnt[b];
#pragma unroll 4
        for (int i = 0; i < n; i++) {
            float4 p = l4[i];                                   // LDS.128
            float rm = lr[i];                                   // LDS.32
            float q  = fmaf(p.x, n2x, fmaf(p.y, n2y, fmaf(p.z, n2z, p.w))); // 3 FFMA
            float d2 = fmaxf(q + r2, 0.0f);                     // FADD + FMNMX(alu)
            float d;
            asm("sqrt.approx.f32 %0, %1;" : "=f"(d) : "f"(d2)); // MUFU
            cmax = fmaxf(cmax, rm - d);                         // FADD + FMNMX(alu)
        }
    }
    if (cmax > 0.0f) atomicMax(&g_key[tid], __float_as_uint(cmax));

    // ---- grid-wide finalize via last-block pattern ---------------------
    __threadfence();
    __syncthreads();
    if (tid == 0) s_last = (atomicAdd(&g_done, 1u) == (unsigned)(NBLK - 1));
    __syncthreads();
    if (s_last) {
        // atomicExch reads the final value AND resets the slot for replay.
        unsigned k = atomicExch(&g_key[tid], 0u);
        float v = __uint_as_float(k);       // cmax >= 0; relu already folded in
#pragma unroll
        for (int o = 16; o > 0; o >>= 1) v += __shfl_xor_sync(0xffffffffu, v, o);
        if ((tid & 31) == 0) s_part[tid >> 5] = v;
        __syncthreads();
        if (tid < 32) {
            float w = (tid < (BT / 32)) ? s_part[tid] : 0.f;
#pragma unroll
            for (int o = 16; o > 0; o >>= 1) w += __shfl_xor_sync(0xffffffffu, w, o);
            if (tid == 0) {
                out[0] = w / (float)BT;
                g_done = 0u;
            }
        }
    }
}

extern "C" void kernel_launch(void* const* d_in, const int* in_sizes, int n_in,
                              void* d_out, int out_size) {
    const float* outputs      = (const float*)d_in[0];
    const float* c2ws         = (const float*)d_in[1];
    const float* scene_scales = (const float*)d_in[2];
    const float* means        = (const float*)d_in[3];
    const float* scales       = (const float*)d_in[4];
    float* out = (float*)d_out;

    size_t smem = (size_t)Bn * PER * (sizeof(float4) + sizeof(float)); // 27040 B
    kMain<<<NBLK, BT, smem>>>(outputs, c2ws, scene_scales, means, scales, out);
}

// round 8
// speedup vs baseline: 1.0966x; 1.0966x over previous
#include <cuda_runtime.h>
#include <cstdint>

#define Bn 8
#define Tn 100
#define BT 800
#define Nn 100000
#define NBLK 592
#define PER 169                 // ceil(Nn / NBLK); 592*169 = 100048
#define NPAIR 85                // ceil((PER+1)/2) pairs per b (padded even)
#define PB 2720                 // NPAIR * 32 bytes per b
#define PAIR_BYTES (Bn * PB)    // 21760
#define MARGINF 0.1f
#define THRESHF 0.5f

// Zero-initialized device state. Invariant: every launch begins AND ends with
// g_key[]==0, g_done==0 (last block resets). cmax >= 0 always, so raw float
// bits are unsigned-monotone; bits(0.0f)==0 matches the zero init.
__device__ unsigned int g_key[BT];
__device__ unsigned int g_done;

__device__ __forceinline__ uint32_t smem_u32(const void* p) {
    uint32_t a;
    asm("{ .reg .u64 t; cvta.to.shared.u64 t, %1; cvt.u32.u64 %0, t; }"
        : "=r"(a) : "l"(p));
    return a;
}

__global__ void __launch_bounds__(BT, 2) kMain(
    const float* __restrict__ outputs,      // (8,100,3)
    const float* __restrict__ c2ws,         // (8,4,4)
    const float* __restrict__ sscales,      // (8,)
    const float* __restrict__ means,        // (100000,3)
    const float* __restrict__ scales,       // (100000,3)
    float* __restrict__ out)
{
    extern __shared__ char sdyn[];
    // [0, PAIR_BYTES): per-b pair blocks {x0,x1,y0,y1 | z0,z1,m20,m21}
    // [PAIR_BYTES, ...): per-b float2 rm pairs (NPAIR per b)
    float2* s_rm = (float2*)(sdyn + PAIR_BYTES);

    __shared__ float s_r[BT * 3];
    __shared__ float s_lo[Bn * 3], s_hi[Bn * 3];
    __shared__ int   s_cnt[Bn];
    __shared__ float s_part[32];
    __shared__ int   s_last;

    const int tid = threadIdx.x;
    const int b   = tid / Tn;

    // ---- prologue: retrajs (each thread its own bt, kept in regs) ------
    float rx, ry, rz;
    {
        float ssb = sscales[b];
        float o0 = outputs[tid * 3 + 0];
        float o1 = outputs[tid * 3 + 1];
        float o2 = outputs[tid * 3 + 2];
        const float* c = c2ws + b * 16;
        rx = fmaf(ssb, o0 * c[0]  + o1 * c[1]  + o2 * c[2],  c[3]);
        ry = fmaf(ssb, o0 * c[4]  + o1 * c[5]  + o2 * c[6],  c[7]);
        rz = fmaf(ssb, o0 * c[8]  + o1 * c[9]  + o2 * c[10], c[11]);
        s_r[tid * 3 + 0] = rx;
        s_r[tid * 3 + 1] = ry;
        s_r[tid * 3 + 2] = rz;
    }
    if (tid < Bn) s_cnt[tid] = 0;
    __syncthreads();

    // ---- per-b boxes: one warp per (b,e), lane-strided + shfl reduce ---
    {
        int w = tid >> 5, l = tid & 31;
        if (w < Bn * 3) {
            int bb = w / 3, e = w % 3;
            float lo = 3.4e38f, hi = -3.4e38f;
            for (int t = l; t < Tn; t += 32) {
                float v = s_r[(bb * Tn + t) * 3 + e];
                lo = fminf(lo, v); hi = fmaxf(hi, v);
            }
#pragma unroll
            for (int o = 16; o > 0; o >>= 1) {
                lo = fminf(lo, __shfl_xor_sync(0xffffffffu, lo, o));
                hi = fmaxf(hi, __shfl_xor_sync(0xffffffffu, hi, o));
            }
            if (l == 0) {
                float thres = THRESHF * sscales[0];
                s_lo[w] = lo - thres;
                s_hi[w] = hi + thres;
            }
        }
    }
    __syncthreads();

    // ---- stage block's slice, compacted per-b, pair-interleaved --------
    {
        int n0 = blockIdx.x * PER;
        int cnt_here = min(Nn - n0, PER);          // <= 169 < BT: single pass
        bool act = tid < cnt_here;
        float mx = 0.f, my = 0.f, mz = 0.f, m2 = 0.f, radM = 0.f;
        if (act) {
            int n = n0 + tid;
            mx = means[n * 3 + 0]; my = means[n * 3 + 1]; mz = means[n * 3 + 2];
            float a0 = scales[n * 3 + 0], a1 = scales[n * 3 + 1], a2 = scales[n * 3 + 2];
            radM = fmaxf(a0, fmaxf(a1, a2)) + MARGINF;
            m2 = fmaf(mx, mx, fmaf(my, my, mz * mz));
        }
        unsigned lmask = (1u << (tid & 31)) - 1u;
#pragma unroll
        for (int bb = 0; bb < Bn; bb++) {
            bool in = act &&
                mx >= s_lo[bb * 3 + 0] && mx <= s_hi[bb * 3 + 0] &&
                my >= s_lo[bb * 3 + 1] && my <= s_hi[bb * 3 + 1] &&
                mz >= s_lo[bb * 3 + 2] && mz <= s_hi[bb * 3 + 2];
            unsigned bal = __ballot_sync(0xffffffffu, in);
            if (bal) {
                int leader = __ffs(bal) - 1;
                int base = 0;
                if ((tid & 31) == leader) base = atomicAdd(&s_cnt[bb], __popc(bal));
                base = __shfl_sync(0xffffffffu, base, leader);
                if (in) {
                    int i = base + __popc(bal & lmask);
                    char* pbp = sdyn + bb * PB + (i >> 1) * 32 + (i & 1) * 4;
                    *(float*)(pbp +  0) = mx;
                    *(float*)(pbp +  8) = my;
                    *(float*)(pbp + 16) = mz;
                    *(float*)(pbp + 24) = m2;
                    ((float*)(s_rm + bb * NPAIR))[i] = radM;
                }
            }
        }
    }
    __syncthreads();

    // ---- pad odd counts by duplicating last point (max is idempotent) --
    if (tid < Bn) {
        int c = s_cnt[tid];
        if (c & 1) {
            int i = c - 1;
            char* src = sdyn + tid * PB + (i >> 1) * 32 + (i & 1) * 4;
            char* dst = sdyn + tid * PB + (c >> 1) * 32 + (c & 1) * 4;
            *(float*)(dst +  0) = *(float*)(src +  0);
            *(float*)(dst +  8) = *(float*)(src +  8);
            *(float*)(dst + 16) = *(float*)(src + 16);
            *(float*)(dst + 24) = *(float*)(src + 24);
            ((float*)(s_rm + tid * NPAIR))[c] = ((float*)(s_rm + tid * NPAIR))[i];
            s_cnt[tid] = c + 1;
        }
    }
    __syncthreads();

    // ---- main loop: 2 points / iter via f32x2 packed math ---------------
    float cmax = 0.0f;
    {
        float n2x = -2.0f * rx, n2y = -2.0f * ry, n2z = -2.0f * rz;
        float r2 = fmaf(rx, rx, fmaf(ry, ry, rz * rz));
        unsigned long long n2x2, n2y2, n2z2, r2p;
        asm("mov.b64 %0, {%1,%1};" : "=l"(n2x2) : "f"(n2x));
        asm("mov.b64 %0, {%1,%1};" : "=l"(n2y2) : "f"(n2y));
        asm("mov.b64 %0, {%1,%1};" : "=l"(n2z2) : "f"(n2z));
        asm("mov.b64 %0, {%1,%1};" : "=l"(r2p)  : "f"(r2));

        uint32_t addr = smem_u32(sdyn) + b * PB;
        const float2* rmp = s_rm + b * NPAIR;
        int npair = s_cnt[b] >> 1;
        float cA = 0.0f, cB = 0.0f;
#pragma unroll 2
        for (int j = 0; j < npair; j++, addr += 32) {
            unsigned long long xx, yy, zz, mm, q, d2p;
            asm("ld.shared.v2.b64 {%0,%1}, [%2];"
                : "=l"(xx), "=l"(yy) : "r"(addr));
            asm("ld.shared.v2.b64 {%0,%1}, [%2];"
                : "=l"(zz), "=l"(mm) : "r"(addr + 16));
            asm("fma.rn.f32x2 %0, %1, %2, %3;" : "=l"(q)   : "l"(zz), "l"(n2z2), "l"(mm));
            asm("fma.rn.f32x2 %0, %1, %2, %3;" : "=l"(q)   : "l"(yy), "l"(n2y2), "l"(q));
            asm("fma.rn.f32x2 %0, %1, %2, %3;" : "=l"(q)   : "l"(xx), "l"(n2x2), "l"(q));
            asm("add.rn.f32x2 %0, %1, %2;"     : "=l"(d2p) : "l"(q),  "l"(r2p));
            float d2a, d2b;
            asm("mov.b64 {%0,%1}, %2;" : "=f"(d2a), "=f"(d2b) : "l"(d2p));
            d2a = fmaxf(d2a, 0.0f);
            d2b = fmaxf(d2b, 0.0f);
            float da, db;
            asm("sqrt.approx.f32 %0, %1;" : "=f"(da) : "f"(d2a));
            asm("sqrt.approx.f32 %0, %1;" : "=f"(db) : "f"(d2b));
            float2 rm = rmp[j];
            cA = fmaxf(cA, rm.x - da);
            cB = fmaxf(cB, rm.y - db);
        }
        cmax = fmaxf(cA, cB);
    }
    if (cmax > 0.0f) atomicMax(&g_key[tid], __float_as_uint(cmax));

    // ---- grid-wide finalize via last-block pattern ---------------------
    __threadfence();
    __syncthreads();
    if (tid == 0) s_last = (atomicAdd(&g_done, 1u) == (unsigned)(NBLK - 1));
    __syncthreads();
    if (s_last) {
        // atomicExch reads the final value AND resets the slot for replay.
        unsigned k = atomicExch(&g_key[tid], 0u);
        float v = __uint_as_float(k);       // cmax >= 0; relu already folded in
#pragma unroll
        for (int o = 16; o > 0; o >>= 1) v += __shfl_xor_sync(0xffffffffu, v, o);
        if ((tid & 31) == 0) s_part[tid >> 5] = v;
        __syncthreads();
        if (tid < 32) {
            float w = (tid < (BT / 32)) ? s_part[tid] : 0.f;
#pragma unroll
            for (int o = 16; o > 0; o >>= 1) w += __shfl_xor_sync(0xffffffffu, w, o);
            if (tid == 0) {
                out[0] = w / (float)BT;
                g_done = 0u;
            }
        }
    }
}

extern "C" void kernel_launch(void* const* d_in, const int* in_sizes, int n_in,
                              void* d_out, int out_size) {
    const float* outputs      = (const float*)d_in[0];
    const float* c2ws         = (const float*)d_in[1];
    const float* scene_scales = (const float*)d_in[2];
    const float* means        = (const float*)d_in[3];
    const float* scales       = (const float*)d_in[4];
    float* out = (float*)d_out;

    size_t smem = PAIR_BYTES + (size_t)Bn * NPAIR * sizeof(float2); // 27200 B
    kMain<<<NBLK, BT, smem>>>(outputs, c2ws, scene_scales, means, scales, out);
}

// round 11
// speedup vs baseline: 1.3403x; 1.2222x over previous
#include <cuda_runtime.h>
#include <cstdint>

#define Bn 8
#define Tn 100
#define BT 800
#define NTHR 400
#define NBLK 443
#define PER 226                 // 443*226 = 100118 >= 100000
#define NPAIR 113               // pairs per b (padded even)
#define PB 3616                 // NPAIR * 32 bytes per b
#define PAIR_BYTES (Bn * PB)    // 28928
#define RM_OFF PAIR_BYTES
#define MARGINF 0.1f
#define THRESHF 0.5f
#define Nn 100000

// Zero-initialized device state; last block resets -> replay-safe.
// cmax >= 0 so raw float bits are unsigned-monotone; bits(0.f)==0 matches init.
__device__ unsigned int g_key[BT];
__device__ unsigned int g_done;

__device__ __forceinline__ uint32_t smem_u32(const void* p) {
    uint32_t a;
    asm("{ .reg .u64 t; cvta.to.shared.u64 t, %1; cvt.u32.u64 %0, t; }"
        : "=r"(a) : "l"(p));
    return a;
}

__global__ void __launch_bounds__(NTHR, 3) kMain(
    const float* __restrict__ outputs,      // (8,100,3)
    const float* __restrict__ c2ws,         // (8,4,4)
    const float* __restrict__ sscales,      // (8,)
    const float* __restrict__ means,        // (100000,3)
    const float* __restrict__ scales,       // (100000,3)
    float* __restrict__ out)
{
    extern __shared__ char sdyn[];
    // [0, PAIR_BYTES): per-b pair blocks {x0,x1,y0,y1 | z0,z1,m20,m21}
    // [RM_OFF, ...):    per-b {rm0,rm1} float pairs

    __shared__ float s_r[BT * 3];           // 9600 B
    __shared__ float s_lo[Bn * 3], s_hi[Bn * 3];
    __shared__ int   s_cnt[Bn];
    __shared__ float s_red[28];
    __shared__ int   s_last;

    const int tid = threadIdx.x;
    const int b   = tid / 50;               // thread covers (b, j) and (b, j+50)
    const int j   = tid % 50;
    const int bt0 = b * Tn + j;
    const int bt1 = bt0 + 50;

    // ---- prologue: two retrajs per thread, kept in regs ----------------
    float rx0, ry0, rz0, rx1, ry1, rz1;
    {
        float ssb = sscales[b];
        const float* c = c2ws + b * 16;
        float a0 = outputs[bt0 * 3 + 0], a1 = outputs[bt0 * 3 + 1], a2 = outputs[bt0 * 3 + 2];
        rx0 = fmaf(ssb, a0 * c[0] + a1 * c[1] + a2 * c[2],  c[3]);
        ry0 = fmaf(ssb, a0 * c[4] + a1 * c[5] + a2 * c[6],  c[7]);
        rz0 = fmaf(ssb, a0 * c[8] + a1 * c[9] + a2 * c[10], c[11]);
        float d0 = outputs[bt1 * 3 + 0], d1 = outputs[bt1 * 3 + 1], d2 = outputs[bt1 * 3 + 2];
        rx1 = fmaf(ssb, d0 * c[0] + d1 * c[1] + d2 * c[2],  c[3]);
        ry1 = fmaf(ssb, d0 * c[4] + d1 * c[5] + d2 * c[6],  c[7]);
        rz1 = fmaf(ssb, d0 * c[8] + d1 * c[9] + d2 * c[10], c[11]);
        s_r[bt0 * 3 + 0] = rx0; s_r[bt0 * 3 + 1] = ry0; s_r[bt0 * 3 + 2] = rz0;
        s_r[bt1 * 3 + 0] = rx1; s_r[bt1 * 3 + 1] = ry1; s_r[bt1 * 3 + 2] = rz1;
    }
    if (tid < Bn) s_cnt[tid] = 0;
    __syncthreads();

    // ---- per-b boxes: 16 lanes per (b,e), shfl reduce within half-group -
    if (tid < Bn * 3 * 16) {                 // 384 threads = warps 0-11, full
        int be = tid / 16, l = tid % 16;
        float lo = 3.4e38f, hi = -3.4e38f;
        int bb = be / 3, e = be % 3;
        for (int t = l; t < Tn; t += 16) {
            float v = s_r[(bb * Tn + t) * 3 + e];
            lo = fminf(lo, v); hi = fmaxf(hi, v);
        }
#pragma unroll
        for (int o = 8; o > 0; o >>= 1) {    // xor stays inside 16-lane half
            lo = fminf(lo, __shfl_xor_sync(0xffffffffu, lo, o));
            hi = fmaxf(hi, __shfl_xor_sync(0xffffffffu, hi, o));
        }
        if (l == 0) {
            float thres = THRESHF * sscales[0];
            s_lo[be] = lo - thres;
            s_hi[be] = hi + thres;
        }
    }
    __syncthreads();

    // ---- stage slice, compacted per-b, pair-interleaved (warps 0-7) ----
    if (tid < 256) {                          // full warps only (ballot-safe)
        int n0 = blockIdx.x * PER;
        int cnt_here = min(Nn - n0, PER);     // may be <=0 for last block
        bool act = tid < cnt_here;
        float mx = 0.f, my = 0.f, mz = 0.f, m2 = 0.f, radM = 0.f;
        if (act) {
            int n = n0 + tid;
            mx = means[n * 3 + 0]; my = means[n * 3 + 1]; mz = means[n * 3 + 2];
            float a0 = scales[n * 3 + 0], a1 = scales[n * 3 + 1], a2 = scales[n * 3 + 2];
            radM = fmaxf(a0, fmaxf(a1, a2)) + MARGINF;
            m2 = fmaf(mx, mx, fmaf(my, my, mz * mz));
        }
        unsigned lmask = (1u << (tid & 31)) - 1u;
#pragma unroll
        for (int bb = 0; bb < Bn; bb++) {
            bool in = act &&
                mx >= s_lo[bb * 3 + 0] && mx <= s_hi[bb * 3 + 0] &&
                my >= s_lo[bb * 3 + 1] && my <= s_hi[bb * 3 + 1] &&
                mz >= s_lo[bb * 3 + 2] && mz <= s_hi[bb * 3 + 2];
            unsigned bal = __ballot_sync(0xffffffffu, in);
            if (bal) {
                int leader = __ffs(bal) - 1;
                int base = 0;
                if ((tid & 31) == leader) base = atomicAdd(&s_cnt[bb], __popc(bal));
                base = __shfl_sync(0xffffffffu, base, leader);
                if (in) {
                    int i = base + __popc(bal & lmask);
                    char* pbp = sdyn + bb * PB + (i >> 1) * 32 + (i & 1) * 4;
                    *(float*)(pbp +  0) = mx;
                    *(float*)(pbp +  8) = my;
                    *(float*)(pbp + 16) = mz;
                    *(float*)(pbp + 24) = m2;
                    *(float*)(sdyn + RM_OFF + bb * (NPAIR * 8) + i * 4) = radM;
                }
            }
        }
    }
    __syncthreads();

    // ---- pad odd counts (max is idempotent) -----------------------------
    if (tid < Bn) {
        int c = s_cnt[tid];
        if (c & 1) {
            int i = c - 1;
            char* src = sdyn + tid * PB + (i >> 1) * 32 + (i & 1) * 4;
            char* dst = sdyn + tid * PB + (c >> 1) * 32 + (c & 1) * 4;
            *(float*)(dst +  0) = *(float*)(src +  0);
            *(float*)(dst +  8) = *(float*)(src +  8);
            *(float*)(dst + 16) = *(float*)(src + 16);
            *(float*)(dst + 24) = *(float*)(src + 24);
            *(float*)(sdyn + RM_OFF + tid * (NPAIR * 8) + c * 4) =
                *(float*)(sdyn + RM_OFF + tid * (NPAIR * 8) + i * 4);
            s_cnt[tid] = c + 1;
        }
    }
    __syncthreads();

    // ---- main loop: 2 points x 2 t's per iter, f32x2 math ---------------
    float cmax0, cmax1;
    {
        unsigned long long X0, Y0, Z0, R0, X1, Y1, Z1, R1;
        {
            float nx0 = -2.f * rx0, ny0 = -2.f * ry0, nz0 = -2.f * rz0;
            float nx1 = -2.f * rx1, ny1 = -2.f * ry1, nz1 = -2.f * rz1;
            float r20 = fmaf(rx0, rx0, fmaf(ry0, ry0, rz0 * rz0));
            float r21 = fmaf(rx1, rx1, fmaf(ry1, ry1, rz1 * rz1));
            asm("mov.b64 %0, {%1,%1};" : "=l"(X0) : "f"(nx0));
            asm("mov.b64 %0, {%1,%1};" : "=l"(Y0) : "f"(ny0));
            asm("mov.b64 %0, {%1,%1};" : "=l"(Z0) : "f"(nz0));
            asm("mov.b64 %0, {%1,%1};" : "=l"(R0) : "f"(r20));
            asm("mov.b64 %0, {%1,%1};" : "=l"(X1) : "f"(nx1));
            asm("mov.b64 %0, {%1,%1};" : "=l"(Y1) : "f"(ny1));
            asm("mov.b64 %0, {%1,%1};" : "=l"(Z1) : "f"(nz1));
            asm("mov.b64 %0, {%1,%1};" : "=l"(R1) : "f"(r21));
        }
        uint32_t base  = smem_u32(sdyn);
        uint32_t addr  = base + b * PB;
        uint32_t rmadr = base + RM_OFF + b * (NPAIR * 8);
        int npair = s_cnt[b] >> 1;
        float cA0 = 0.f, cB0 = 0.f, cA1 = 0.f, cB1 = 0.f;
#pragma unroll 2
        for (int i = 0; i < npair; i++, addr += 32, rmadr += 8) {
            unsigned long long xx, yy, zz, mm, q0, q1, p0, p1;
            float rm0, rm1;
            asm("ld.shared.v2.b64 {%0,%1}, [%2];" : "=l"(xx), "=l"(yy) : "r"(addr));
            asm("ld.shared.v2.b64 {%0,%1}, [%2];" : "=l"(zz), "=l"(mm) : "r"(addr + 16));
            asm("ld.shared.v2.f32 {%0,%1}, [%2];" : "=f"(rm0), "=f"(rm1) : "r"(rmadr));
            // t0
            asm("fma.rn.f32x2 %0, %1, %2, %3;" : "=l"(q0) : "l"(zz), "l"(Z0), "l"(mm));
            asm("fma.rn.f32x2 %0, %1, %2, %3;" : "=l"(q0) : "l"(yy), "l"(Y0), "l"(q0));
            asm("fma.rn.f32x2 %0, %1, %2, %3;" : "=l"(q0) : "l"(xx), "l"(X0), "l"(q0));
            asm("add.rn.f32x2 %0, %1, %2;"     : "=l"(p0) : "l"(q0), "l"(R0));
            // t1
            asm("fma.rn.f32x2 %0, %1, %2, %3;" : "=l"(q1) : "l"(zz), "l"(Z1), "l"(mm));
            asm("fma.rn.f32x2 %0, %1, %2, %3;" : "=l"(q1) : "l"(yy), "l"(Y1), "l"(q1));
            asm("fma.rn.f32x2 %0, %1, %2, %3;" : "=l"(q1) : "l"(xx), "l"(X1), "l"(q1));
            asm("add.rn.f32x2 %0, %1, %2;"     : "=l"(p1) : "l"(q1), "l"(R1));
            float a0, b0f, a1, b1f, da0, db0, da1, db1;
            asm("mov.b64 {%0,%1}, %2;" : "=f"(a0), "=f"(b0f) : "l"(p0));
            asm("mov.b64 {%0,%1}, %2;" : "=f"(a1), "=f"(b1f) : "l"(p1));
            // d2 >= 0 up to rounding; a negative would give NaN which fmaxf drops.
            asm("sqrt.approx.f32 %0, %1;" : "=f"(da0) : "f"(a0));
            asm("sqrt.approx.f32 %0, %1;" : "=f"(db0) : "f"(b0f));
            asm("sqrt.approx.f32 %0, %1;" : "=f"(da1) : "f"(a1));
            asm("sqrt.approx.f32 %0, %1;" : "=f"(db1) : "f"(b1f));
            cA0 = fmaxf(cA0, rm0 - da0);
            cB0 = fmaxf(cB0, rm1 - db0);
            cA1 = fmaxf(cA1, rm0 - da1);
            cB1 = fmaxf(cB1, rm1 - db1);
        }
        cmax0 = fmaxf(cA0, cB0);
        cmax1 = fmaxf(cA1, cB1);
    }
    if (cmax0 > 0.0f) atomicMax(&g_key[bt0], __float_as_uint(cmax0));
    if (cmax1 > 0.0f) atomicMax(&g_key[bt1], __float_as_uint(cmax1));

    // ---- grid-wide finalize via last-block pattern ----------------------
    __threadfence();
    __syncthreads();
    if (tid == 0) s_last = (atomicAdd(&g_done, 1u) == (unsigned)(NBLK - 1));
    __syncthreads();
    if (s_last) {
        unsigned k0 = atomicExch(&g_key[tid], 0u);         // read + reset
        unsigned k1 = atomicExch(&g_key[tid + NTHR], 0u);
        float v = __uint_as_float(k0) + __uint_as_float(k1);
        int w = tid >> 5, l = tid & 31;
        if (w < 12) {                                       // full warps
#pragma unroll
            for (int o = 16; o > 0; o >>= 1) v += __shfl_xor_sync(0xffffffffu, v, o);
            if (l == 0) s_red[w] = v;
        } else {                                            // warp 12: 16 lanes
            s_red[12 + l] = v;
        }
        __syncthreads();
        if (tid < 32) {
            float x = (tid < 28) ? s_red[tid] : 0.f;
#pragma unroll
            for (int o = 16; o > 0; o >>= 1) x += __shfl_xor_sync(0xffffffffu, x, o);
            if (tid == 0) {
                out[0] = x / (float)BT;
                g_done = 0u;
            }
        }
    }
}

extern "C" void kernel_launch(void* const* d_in, const int* in_sizes, int n_in,
                              void* d_out, int out_size) {
    const float* outputs      = (const float*)d_in[0];
    const float* c2ws         = (const float*)d_in[1];
    const float* scene_scales = (const float*)d_in[2];
    const float* means        = (const float*)d_in[3];
    const float* scales       = (const float*)d_in[4];
    float* out = (float*)d_out;

    size_t smem = PAIR_BYTES + (size_t)Bn * NPAIR * 8;   // 28928 + 7232 = 36160 B
    kMain<<<NBLK, NTHR, smem>>>(outputs, c2ws, scene_scales, means, scales, out);
}